// round 2
// baseline (speedup 1.0000x reference)
#include <cuda_runtime.h>
#include <cstdint>

#define N_NODES 50000
#define IN_FEAT 128
#define OUT_FEAT 128
#define K_TOT 256   // 2*IN_FEAT

// ---- scratch (device globals; no allocation allowed) ----
__device__ float g_agg[N_NODES * IN_FEAT];   // 25.6 MB
__device__ float g_deg[N_NODES];
__device__ float g_inv[N_NODES];
__device__ float g_Wt[K_TOT * OUT_FEAT];     // W transposed: Wt[k][j] = W[j][k]
__device__ int   g_is64;                      // 1 if src/dst are int64

// ---------------------------------------------------------------------------
// 0) detect index dtype: int32 array read as int64 yields huge values
// ---------------------------------------------------------------------------
__global__ void detect_kernel(const void* __restrict__ src, int n) {
    if (threadIdx.x == 0 && blockIdx.x == 0) {
        const long long* p = (const long long*)src;
        int is64 = 1;
        int lim = n < 64 ? n : 64;
        for (int i = 0; i < lim; i++) {
            long long v = p[i];
            if (v < 0 || v >= (long long)N_NODES) { is64 = 0; break; }
        }
        g_is64 = is64;
    }
}

// ---------------------------------------------------------------------------
// 1) zero agg + deg
// ---------------------------------------------------------------------------
__global__ void zero_kernel() {
    const int total = N_NODES * IN_FEAT;
    for (int i = blockIdx.x * blockDim.x + threadIdx.x; i < total;
         i += gridDim.x * blockDim.x) {
        g_agg[i] = 0.0f;
        if (i < N_NODES) g_deg[i] = 0.0f;
    }
}

// ---------------------------------------------------------------------------
// 2) per-edge scatter: one warp per edge, float4 vector reductions into L2
// ---------------------------------------------------------------------------
__global__ void scatter_kernel(const float* __restrict__ h,
                               const void* __restrict__ src_raw,
                               const void* __restrict__ dst_raw,
                               int n_edges) {
    int gw   = (blockIdx.x * blockDim.x + threadIdx.x) >> 5;  // global warp = edge
    int lane = threadIdx.x & 31;
    if (gw >= n_edges) return;

    int s, d;
    if (g_is64) {
        s = (int)((const long long*)src_raw)[gw];
        d = (int)((const long long*)dst_raw)[gw];
    } else {
        s = ((const int*)src_raw)[gw];
        d = ((const int*)dst_raw)[gw];
    }
    // safety clamp: wrong index -> wrong answer (diagnosable), not a crash
    s = min(max(s, 0), N_NODES - 1);
    d = min(max(d, 0), N_NODES - 1);

    const float4* hv = reinterpret_cast<const float4*>(h + (size_t)s * IN_FEAT);
    float4 v = hv[lane];

    float* a = g_agg + (size_t)d * IN_FEAT + lane * 4;
    asm volatile("red.global.add.v4.f32 [%0], {%1, %2, %3, %4};"
                 :: "l"(a), "f"(v.x), "f"(v.y), "f"(v.z), "f"(v.w)
                 : "memory");

    if (lane == 0) atomicAdd(&g_deg[d], 1.0f);
}

// ---------------------------------------------------------------------------
// 3) inv = 1 / max(deg, 1)
// ---------------------------------------------------------------------------
__global__ void inv_kernel() {
    int i = blockIdx.x * blockDim.x + threadIdx.x;
    if (i < N_NODES) g_inv[i] = 1.0f / fmaxf(g_deg[i], 1.0f);
}

// ---------------------------------------------------------------------------
// 4) transpose W (tiny: 128x256)
// ---------------------------------------------------------------------------
__global__ void transpose_w_kernel(const float* __restrict__ W) {
    int idx = blockIdx.x * blockDim.x + threadIdx.x;  // over K_TOT*OUT_FEAT
    if (idx < K_TOT * OUT_FEAT) {
        int j = idx % OUT_FEAT;
        int k = idx / OUT_FEAT;
        g_Wt[idx] = W[j * K_TOT + k];
    }
}

// ---------------------------------------------------------------------------
// 5) fused GEMM: out[n][j] = b[j] + sum_k A[n][k] * Wt[k][j]
//    A[n][k] = h[n][k]              (k < 128)
//            = g_agg[n][k-128]*inv  (k >= 128)   -- concat fused into load
// ---------------------------------------------------------------------------
#define BM 128
#define BN 128
#define BK 8
#define TM 8

__global__ __launch_bounds__(256, 2)
void gemm_kernel(const float* __restrict__ h,
                 const float* __restrict__ bias,
                 float* __restrict__ out) {
    __shared__ float As[BK][BM];          // A tile transposed: As[k][row]
    __shared__ float Bs[BK][BN];
    __shared__ float sInv[BM];

    const int tid = threadIdx.x;
    const int tx  = tid & 15;             // 0..15
    const int ty  = tid >> 4;             // 0..15
    const int block_row = blockIdx.x * BM;

    if (tid < BM) {
        int r = block_row + tid;
        sInv[tid] = (r < N_NODES) ? g_inv[r] : 0.0f;
    }
    __syncthreads();

    const int a_row = tid >> 1;           // 0..127
    const int a_k4  = (tid & 1) * 4;      // 0 or 4
    const int grow  = block_row + a_row;
    const bool rvalid = (grow < N_NODES);
    const float rinv = sInv[a_row];

    const int b_k   = tid >> 5;           // 0..7
    const int b_col = (tid & 31) * 4;     // 0..124

    float acc[TM][8];
    #pragma unroll
    for (int i = 0; i < TM; i++)
        #pragma unroll
        for (int j = 0; j < 8; j++) acc[i][j] = 0.0f;

    const int row_base = ty * TM;
    const int c0 = tx * 4;
    const int c1 = 64 + tx * 4;

    for (int k0 = 0; k0 < K_TOT; k0 += BK) {
        float4 av = make_float4(0.f, 0.f, 0.f, 0.f);
        const int k = k0 + a_k4;
        if (rvalid) {
            if (k < IN_FEAT) {
                av = *reinterpret_cast<const float4*>(
                        h + (size_t)grow * IN_FEAT + k);
            } else {
                av = *reinterpret_cast<const float4*>(
                        g_agg + (size_t)grow * IN_FEAT + (k - IN_FEAT));
                av.x *= rinv; av.y *= rinv; av.z *= rinv; av.w *= rinv;
            }
        }
        As[a_k4 + 0][a_row] = av.x;
        As[a_k4 + 1][a_row] = av.y;
        As[a_k4 + 2][a_row] = av.z;
        As[a_k4 + 3][a_row] = av.w;

        *reinterpret_cast<float4*>(&Bs[b_k][b_col]) =
            *reinterpret_cast<const float4*>(
                g_Wt + (size_t)(k0 + b_k) * OUT_FEAT + b_col);

        __syncthreads();

        #pragma unroll
        for (int kk = 0; kk < BK; kk++) {
            float ra[TM];
            float4 rb0 = *reinterpret_cast<const float4*>(&Bs[kk][c0]);
            float4 rb1 = *reinterpret_cast<const float4*>(&Bs[kk][c1]);
            float4 ra0 = *reinterpret_cast<const float4*>(&As[kk][row_base]);
            float4 ra1 = *reinterpret_cast<const float4*>(&As[kk][row_base + 4]);
            ra[0] = ra0.x; ra[1] = ra0.y; ra[2] = ra0.z; ra[3] = ra0.w;
            ra[4] = ra1.x; ra[5] = ra1.y; ra[6] = ra1.z; ra[7] = ra1.w;
            #pragma unroll
            for (int i = 0; i < TM; i++) {
                acc[i][0] = fmaf(ra[i], rb0.x, acc[i][0]);
                acc[i][1] = fmaf(ra[i], rb0.y, acc[i][1]);
                acc[i][2] = fmaf(ra[i], rb0.z, acc[i][2]);
                acc[i][3] = fmaf(ra[i], rb0.w, acc[i][3]);
                acc[i][4] = fmaf(ra[i], rb1.x, acc[i][4]);
                acc[i][5] = fmaf(ra[i], rb1.y, acc[i][5]);
                acc[i][6] = fmaf(ra[i], rb1.z, acc[i][6]);
                acc[i][7] = fmaf(ra[i], rb1.w, acc[i][7]);
            }
        }
        __syncthreads();
    }

    const float4 bv0 = *reinterpret_cast<const float4*>(bias + c0);
    const float4 bv1 = *reinterpret_cast<const float4*>(bias + c1);
    #pragma unroll
    for (int i = 0; i < TM; i++) {
        int r = block_row + row_base + i;
        if (r < N_NODES) {
            float4 o0 = make_float4(acc[i][0] + bv0.x, acc[i][1] + bv0.y,
                                    acc[i][2] + bv0.z, acc[i][3] + bv0.w);
            float4 o1 = make_float4(acc[i][4] + bv1.x, acc[i][5] + bv1.y,
                                    acc[i][6] + bv1.z, acc[i][7] + bv1.w);
            *reinterpret_cast<float4*>(out + (size_t)r * OUT_FEAT + c0) = o0;
            *reinterpret_cast<float4*>(out + (size_t)r * OUT_FEAT + c1) = o1;
        }
    }
}

// ---------------------------------------------------------------------------
extern "C" void kernel_launch(void* const* d_in, const int* in_sizes, int n_in,
                              void* d_out, int out_size) {
    const float* h   = (const float*)d_in[0];
    const void*  src = d_in[1];
    const void*  dst = d_in[2];
    const float* W   = (const float*)d_in[3];
    const float* b   = (const float*)d_in[4];
    float*       out = (float*)d_out;

    const int n_edges = in_sizes[1];

    detect_kernel<<<1, 32>>>(src, n_edges);

    zero_kernel<<<4096, 256>>>();

    transpose_w_kernel<<<(K_TOT * OUT_FEAT + 255) / 256, 256>>>(W);

    // one warp per edge
    int blocks = (n_edges + 7) / 8;  // 8 warps / 256 threads per block
    scatter_kernel<<<blocks, 256>>>(h, src, dst, n_edges);

    inv_kernel<<<(N_NODES + 255) / 256, 256>>>();

    gemm_kernel<<<(N_NODES + BM - 1) / BM, 256>>>(h, b, out);
}

// round 4
// speedup vs baseline: 2.0379x; 2.0379x over previous
#include <cuda_runtime.h>
#include <cstdint>

#define N_NODES 50000
#define N_EDGES_MAX 800000
#define IN_FEAT 128
#define OUT_FEAT 128
#define K_TOT 256

// ---------------- device scratch (no allocation allowed) ----------------
__device__ float g_hn[N_NODES * IN_FEAT];     // mean-aggregated neighbor feats
__device__ int   g_count[N_NODES];
__device__ int   g_cursor[N_NODES];
__device__ int   g_off[N_NODES + 1];
__device__ int   g_esrc[N_EDGES_MAX];
__device__ int   g_is64;

// ---------------------------------------------------------------------------
// 0) index dtype detection (int64 vs int32 materialization)
// ---------------------------------------------------------------------------
__global__ void detect_kernel(const void* __restrict__ src, int n) {
    if (threadIdx.x == 0 && blockIdx.x == 0) {
        const long long* p = (const long long*)src;
        int is64 = 1;
        int lim = n < 64 ? n : 64;
        for (int i = 0; i < lim; i++) {
            long long v = p[i];
            if (v < 0 || v >= (long long)N_NODES) { is64 = 0; break; }
        }
        g_is64 = is64;
    }
}

__device__ __forceinline__ int load_idx(const void* raw, int i) {
    int v = g_is64 ? (int)((const long long*)raw)[i] : ((const int*)raw)[i];
    return min(max(v, 0), N_NODES - 1);
}

// ---------------------------------------------------------------------------
// 1) zero counters
// ---------------------------------------------------------------------------
__global__ void zero_kernel() {
    int i = blockIdx.x * blockDim.x + threadIdx.x;
    if (i < N_NODES) { g_count[i] = 0; g_cursor[i] = 0; }
}

// ---------------------------------------------------------------------------
// 2) degree histogram
// ---------------------------------------------------------------------------
__global__ void count_kernel(const void* __restrict__ dst, int n_edges) {
    int i = blockIdx.x * blockDim.x + threadIdx.x;
    if (i < n_edges) atomicAdd(&g_count[load_idx(dst, i)], 1);
}

// ---------------------------------------------------------------------------
// 3) exclusive scan over 50000 counts (single block)
// ---------------------------------------------------------------------------
__global__ void scan_kernel() {
    __shared__ int part[1024];
    const int CH = (N_NODES + 1023) / 1024;   // 49
    int t = threadIdx.x;
    int start = t * CH;
    int end = min(start + CH, N_NODES);
    int sum = 0;
    for (int i = start; i < end; i++) sum += g_count[i];
    part[t] = sum;
    __syncthreads();
    for (int off = 1; off < 1024; off <<= 1) {
        int v = (t >= off) ? part[t - off] : 0;
        __syncthreads();
        part[t] += v;
        __syncthreads();
    }
    int run = part[t] - sum;                  // exclusive prefix of this chunk
    for (int i = start; i < end; i++) { g_off[i] = run; run += g_count[i]; }
    if (t == 1023) g_off[N_NODES] = part[1023];
}

// ---------------------------------------------------------------------------
// 4) fill per-dst CSR edge lists
// ---------------------------------------------------------------------------
__global__ void fill_kernel(const void* __restrict__ src, const void* __restrict__ dst,
                            int n_edges) {
    int i = blockIdx.x * blockDim.x + threadIdx.x;
    if (i < n_edges) {
        int d = load_idx(dst, i);
        int s = load_idx(src, i);
        int pos = g_off[d] + atomicAdd(&g_cursor[d], 1);
        g_esrc[pos] = s;
    }
}

// ---------------------------------------------------------------------------
// 5) aggregate: one warp per node, register accumulation, write scaled mean
// ---------------------------------------------------------------------------
__global__ void aggregate_kernel(const float* __restrict__ h) {
    int node = (blockIdx.x * blockDim.x + threadIdx.x) >> 5;
    int lane = threadIdx.x & 31;
    if (node >= N_NODES) return;

    int beg = g_off[node];
    int end = g_off[node + 1];
    int cnt = end - beg;

    float4 acc = make_float4(0.f, 0.f, 0.f, 0.f);
    if (cnt > 0) {
        int s = g_esrc[beg];
        for (int i = beg; i + 1 < end; i++) {
            int s2 = g_esrc[i + 1];                    // prefetch next index
            float4 v = reinterpret_cast<const float4*>(h + (size_t)s * IN_FEAT)[lane];
            acc.x += v.x; acc.y += v.y; acc.z += v.z; acc.w += v.w;
            s = s2;
        }
        float4 v = reinterpret_cast<const float4*>(h + (size_t)s * IN_FEAT)[lane];
        acc.x += v.x; acc.y += v.y; acc.z += v.z; acc.w += v.w;
    }
    float inv = 1.0f / fmaxf((float)cnt, 1.0f);
    acc.x *= inv; acc.y *= inv; acc.z *= inv; acc.w *= inv;
    reinterpret_cast<float4*>(g_hn + (size_t)node * IN_FEAT)[lane] = acc;
}

// ---------------------------------------------------------------------------
// 6) tf32 mma.sync GEMM: out[128 x 128] per CTA = [h | g_hn] @ W^T + b
// 256 threads / 8 warps; warp grid 4(m) x 2(n); warp tile 32x64; m16n8k8.
// ---------------------------------------------------------------------------
#define BM 128
#define BK 32
#define LDT 36   // padded shared stride: bank = (4*group + tg) -> conflict-free

__device__ __forceinline__ float to_tf32(float x) {
    float y;
    asm("cvt.rna.tf32.f32 %0, %1;" : "=f"(y) : "f"(x));
    return y;
}

__device__ __forceinline__ void mma_tf32(float* d, const uint32_t* a, const uint32_t* b) {
    asm volatile(
        "mma.sync.aligned.m16n8k8.row.col.f32.tf32.tf32.f32 "
        "{%0,%1,%2,%3}, {%4,%5,%6,%7}, {%8,%9}, {%0,%1,%2,%3};"
        : "+f"(d[0]), "+f"(d[1]), "+f"(d[2]), "+f"(d[3])
        : "r"(a[0]), "r"(a[1]), "r"(a[2]), "r"(a[3]), "r"(b[0]), "r"(b[1]));
}

__global__ __launch_bounds__(256, 2)
void gemm_mma_kernel(const float* __restrict__ h,
                     const float* __restrict__ W,     // [128, 256] row-major
                     const float* __restrict__ bias,
                     float* __restrict__ out) {
    __shared__ float As[BM * LDT];   // A tile [m][k], stride 36
    __shared__ float Ws[BM * LDT];   // W tile [n][k], stride 36
    __shared__ float sb[OUT_FEAT];

    const int tid  = threadIdx.x;
    const int wid  = tid >> 5;
    const int lane = tid & 31;
    const int group = lane >> 2;     // 0..7
    const int tg    = lane & 3;      // 0..3
    const int block_row = blockIdx.x * BM;

    const int warp_m = (wid & 3) * 32;   // 0,32,64,96
    const int warp_n = (wid >> 2) * 64;  // 0,64

    if (tid < OUT_FEAT) sb[tid] = bias[tid];

    // loader mapping: 2 threads per row, 16 floats each
    const int l_row = tid >> 1;          // 0..127
    const int l_kh  = (tid & 1) * 16;    // 0 or 16
    const int grow  = block_row + l_row;
    const bool rvalid = (grow < N_NODES);

    float acc[2][8][4];
    #pragma unroll
    for (int mt = 0; mt < 2; mt++)
        #pragma unroll
        for (int nt = 0; nt < 8; nt++)
            #pragma unroll
            for (int r = 0; r < 4; r++) acc[mt][nt][r] = 0.0f;

    for (int c = 0; c < K_TOT / BK; c++) {         // 8 chunks
        const int k0 = c * BK;
        __syncthreads();                            // smem reusable

        // ---- A tile (fused concat: h | g_hn, both pre-scaled) ----
        {
            const int k = k0 + l_kh;                // half stays within one source
            const float* asrc = (k < IN_FEAT)
                ? (h    + (size_t)grow * IN_FEAT + k)
                : (g_hn + (size_t)grow * IN_FEAT + (k - IN_FEAT));
            float* dsta = &As[l_row * LDT + l_kh];
            #pragma unroll
            for (int i = 0; i < 4; i++) {
                float4 v = rvalid ? reinterpret_cast<const float4*>(asrc)[i]
                                  : make_float4(0.f, 0.f, 0.f, 0.f);
                dsta[i * 4 + 0] = to_tf32(v.x);
                dsta[i * 4 + 1] = to_tf32(v.y);
                dsta[i * 4 + 2] = to_tf32(v.z);
                dsta[i * 4 + 3] = to_tf32(v.w);
            }
        }
        // ---- W tile ----
        {
            const float* bsrc = W + (size_t)l_row * K_TOT + k0 + l_kh;
            float* dstb = &Ws[l_row * LDT + l_kh];
            #pragma unroll
            for (int i = 0; i < 4; i++) {
                float4 v = reinterpret_cast<const float4*>(bsrc)[i];
                dstb[i * 4 + 0] = to_tf32(v.x);
                dstb[i * 4 + 1] = to_tf32(v.y);
                dstb[i * 4 + 2] = to_tf32(v.z);
                dstb[i * 4 + 3] = to_tf32(v.w);
            }
        }
        __syncthreads();

        #pragma unroll
        for (int ks = 0; ks < 4; ks++) {            // 4 x k8 per chunk
            const int k8 = ks * 8;
            uint32_t afr[2][4], bfr[8][2];
            #pragma unroll
            for (int mt = 0; mt < 2; mt++) {
                const float* ap = &As[(warp_m + mt * 16 + group) * LDT + k8];
                afr[mt][0] = __float_as_uint(ap[tg]);
                afr[mt][1] = __float_as_uint(ap[8 * LDT + tg]);
                afr[mt][2] = __float_as_uint(ap[tg + 4]);
                afr[mt][3] = __float_as_uint(ap[8 * LDT + tg + 4]);
            }
            #pragma unroll
            for (int nt = 0; nt < 8; nt++) {
                const float* bp = &Ws[(warp_n + nt * 8 + group) * LDT + k8];
                bfr[nt][0] = __float_as_uint(bp[tg]);
                bfr[nt][1] = __float_as_uint(bp[tg + 4]);
            }
            #pragma unroll
            for (int mt = 0; mt < 2; mt++)
                #pragma unroll
                for (int nt = 0; nt < 8; nt++)
                    mma_tf32(acc[mt][nt], afr[mt], bfr[nt]);
        }
    }

    // ---- epilogue: bias + float2 stores ----
    #pragma unroll
    for (int mt = 0; mt < 2; mt++) {
        const int r0 = block_row + warp_m + mt * 16 + group;
        const int r1 = r0 + 8;
        #pragma unroll
        for (int nt = 0; nt < 8; nt++) {
            const int col = warp_n + nt * 8 + tg * 2;
            const float b0 = sb[col], b1 = sb[col + 1];
            if (r0 < N_NODES) {
                float2 o = make_float2(acc[mt][nt][0] + b0, acc[mt][nt][1] + b1);
                *reinterpret_cast<float2*>(out + (size_t)r0 * OUT_FEAT + col) = o;
            }
            if (r1 < N_NODES) {
                float2 o = make_float2(acc[mt][nt][2] + b0, acc[mt][nt][3] + b1);
                *reinterpret_cast<float2*>(out + (size_t)r1 * OUT_FEAT + col) = o;
            }
        }
    }
}

// ---------------------------------------------------------------------------
extern "C" void kernel_launch(void* const* d_in, const int* in_sizes, int n_in,
                              void* d_out, int out_size) {
    const float* h   = (const float*)d_in[0];
    const void*  src = d_in[1];
    const void*  dst = d_in[2];
    const float* W   = (const float*)d_in[3];
    const float* b   = (const float*)d_in[4];
    float*       out = (float*)d_out;

    const int n_edges = in_sizes[1];

    detect_kernel<<<1, 32>>>(src, n_edges);
    zero_kernel<<<(N_NODES + 255) / 256, 256>>>();
    count_kernel<<<(n_edges + 255) / 256, 256>>>(dst, n_edges);
    scan_kernel<<<1, 1024>>>();
    fill_kernel<<<(n_edges + 255) / 256, 256>>>(src, dst, n_edges);
    aggregate_kernel<<<(N_NODES * 32 + 255) / 256, 256>>>(h);
    gemm_mma_kernel<<<(N_NODES + BM - 1) / BM, 256>>>(h, W, b, out);
}

// round 5
// speedup vs baseline: 2.7885x; 1.3683x over previous
#include <cuda_runtime.h>
#include <cstdint>

#define N_NODES 50000
#define N_EDGES_MAX 800000
#define IN_FEAT 128
#define OUT_FEAT 128
#define K_TOT 256

#define SCAN_BLK 512
#define NB_SCAN ((N_NODES + SCAN_BLK - 1) / SCAN_BLK)   // 98

// ---------------- device scratch (no allocation allowed) ----------------
__device__ float g_hn[N_NODES * IN_FEAT];     // mean-aggregated neighbor feats
__device__ int   g_count[N_NODES];
__device__ int   g_cursor[N_NODES];
__device__ int   g_off[N_NODES + 1];
__device__ int   g_esrc[N_EDGES_MAX];
__device__ int   g_bsum[NB_SCAN];
__device__ int   g_bbase[NB_SCAN];
__device__ int   g_is64;

// ---------------------------------------------------------------------------
// 0) index dtype detection (int64 vs int32 materialization)
// ---------------------------------------------------------------------------
__global__ void detect_kernel(const void* __restrict__ src, int n) {
    if (threadIdx.x == 0 && blockIdx.x == 0) {
        const long long* p = (const long long*)src;
        int is64 = 1;
        int lim = n < 64 ? n : 64;
        for (int i = 0; i < lim; i++) {
            long long v = p[i];
            if (v < 0 || v >= (long long)N_NODES) { is64 = 0; break; }
        }
        g_is64 = is64;
    }
}

__device__ __forceinline__ int load_idx(const void* raw, int i) {
    int v = g_is64 ? (int)((const long long*)raw)[i] : ((const int*)raw)[i];
    return min(max(v, 0), N_NODES - 1);
}

// ---------------------------------------------------------------------------
// 1) zero counters
// ---------------------------------------------------------------------------
__global__ void zero_kernel() {
    int i = blockIdx.x * blockDim.x + threadIdx.x;
    if (i < N_NODES) { g_count[i] = 0; g_cursor[i] = 0; }
}

// ---------------------------------------------------------------------------
// 2) degree histogram
// ---------------------------------------------------------------------------
__global__ void count_kernel(const void* __restrict__ dst, int n_edges) {
    int i = blockIdx.x * blockDim.x + threadIdx.x;
    if (i < n_edges) atomicAdd(&g_count[load_idx(dst, i)], 1);
}

// ---------------------------------------------------------------------------
// 3) exclusive scan, 3-phase multi-block
// ---------------------------------------------------------------------------
__global__ void scan_phase1() {
    int i = blockIdx.x * SCAN_BLK + threadIdx.x;
    int v = (i < N_NODES) ? g_count[i] : 0;
    __shared__ int ws[SCAN_BLK / 32];
    int lane = threadIdx.x & 31, w = threadIdx.x >> 5;
    #pragma unroll
    for (int o = 16; o > 0; o >>= 1) v += __shfl_down_sync(~0u, v, o);
    if (lane == 0) ws[w] = v;
    __syncthreads();
    if (w == 0) {
        int s = (lane < SCAN_BLK / 32) ? ws[lane] : 0;
        #pragma unroll
        for (int o = 16; o > 0; o >>= 1) s += __shfl_down_sync(~0u, s, o);
        if (lane == 0) g_bsum[blockIdx.x] = s;
    }
}

__global__ void scan_phase2() {          // 1 block, 32 threads
    int lane = threadIdx.x;
    int run = 0;
    for (int base = 0; base < NB_SCAN; base += 32) {
        int idx = base + lane;
        int v = (idx < NB_SCAN) ? g_bsum[idx] : 0;
        int inc = v;
        #pragma unroll
        for (int o = 1; o < 32; o <<= 1) {
            int t = __shfl_up_sync(~0u, inc, o);
            if (lane >= o) inc += t;
        }
        if (idx < NB_SCAN) g_bbase[idx] = inc - v + run;
        run += __shfl_sync(~0u, inc, 31);
    }
    if (lane == 0) g_off[N_NODES] = run;
}

__global__ void scan_phase3() {
    int i = blockIdx.x * SCAN_BLK + threadIdx.x;
    int v = (i < N_NODES) ? g_count[i] : 0;
    __shared__ int ws[SCAN_BLK / 32];
    int lane = threadIdx.x & 31, w = threadIdx.x >> 5;
    int inc = v;
    #pragma unroll
    for (int o = 1; o < 32; o <<= 1) {
        int t = __shfl_up_sync(~0u, inc, o);
        if (lane >= o) inc += t;
    }
    if (lane == 31) ws[w] = inc;
    __syncthreads();
    if (w == 0) {
        int s = (lane < SCAN_BLK / 32) ? ws[lane] : 0;
        int sin = s;
        #pragma unroll
        for (int o = 1; o < 32; o <<= 1) {
            int t = __shfl_up_sync(~0u, sin, o);
            if (lane >= o) sin += t;
        }
        if (lane < SCAN_BLK / 32) ws[lane] = sin - s;   // exclusive warp base
    }
    __syncthreads();
    if (i < N_NODES) g_off[i] = inc - v + ws[w] + g_bbase[blockIdx.x];
}

// ---------------------------------------------------------------------------
// 4) fill per-dst CSR edge lists
// ---------------------------------------------------------------------------
__global__ void fill_kernel(const void* __restrict__ src, const void* __restrict__ dst,
                            int n_edges) {
    int i = blockIdx.x * blockDim.x + threadIdx.x;
    if (i < n_edges) {
        int d = load_idx(dst, i);
        int s = load_idx(src, i);
        int pos = g_off[d] + atomicAdd(&g_cursor[d], 1);
        g_esrc[pos] = s;
    }
}

// ---------------------------------------------------------------------------
// 5) aggregate: one warp per node, 2-way unrolled register accumulation
// ---------------------------------------------------------------------------
__global__ void aggregate_kernel(const float* __restrict__ h) {
    int node = (blockIdx.x * blockDim.x + threadIdx.x) >> 5;
    int lane = threadIdx.x & 31;
    if (node >= N_NODES) return;

    int beg = g_off[node];
    int end = g_off[node + 1];
    int cnt = end - beg;

    float4 acc0 = make_float4(0.f, 0.f, 0.f, 0.f);
    float4 acc1 = make_float4(0.f, 0.f, 0.f, 0.f);
    int i = beg;
    for (; i + 1 < end; i += 2) {
        int s0 = g_esrc[i];
        int s1 = g_esrc[i + 1];
        float4 v0 = reinterpret_cast<const float4*>(h + (size_t)s0 * IN_FEAT)[lane];
        float4 v1 = reinterpret_cast<const float4*>(h + (size_t)s1 * IN_FEAT)[lane];
        acc0.x += v0.x; acc0.y += v0.y; acc0.z += v0.z; acc0.w += v0.w;
        acc1.x += v1.x; acc1.y += v1.y; acc1.z += v1.z; acc1.w += v1.w;
    }
    if (i < end) {
        int s = g_esrc[i];
        float4 v = reinterpret_cast<const float4*>(h + (size_t)s * IN_FEAT)[lane];
        acc0.x += v.x; acc0.y += v.y; acc0.z += v.z; acc0.w += v.w;
    }
    float inv = 1.0f / fmaxf((float)cnt, 1.0f);
    acc0.x = (acc0.x + acc1.x) * inv;
    acc0.y = (acc0.y + acc1.y) * inv;
    acc0.z = (acc0.z + acc1.z) * inv;
    acc0.w = (acc0.w + acc1.w) * inv;
    reinterpret_cast<float4*>(g_hn + (size_t)node * IN_FEAT)[lane] = acc0;
}

// ---------------------------------------------------------------------------
// 6) tf32 mma.sync GEMM: out[128 x 128] per CTA = [h | g_hn] @ W^T + b
// ---------------------------------------------------------------------------
#define BM 128
#define BK 32
#define LDT 36

__device__ __forceinline__ float to_tf32(float x) {
    float y;
    asm("cvt.rna.tf32.f32 %0, %1;" : "=f"(y) : "f"(x));
    return y;
}

__device__ __forceinline__ void mma_tf32(float* d, const uint32_t* a, const uint32_t* b) {
    asm volatile(
        "mma.sync.aligned.m16n8k8.row.col.f32.tf32.tf32.f32 "
        "{%0,%1,%2,%3}, {%4,%5,%6,%7}, {%8,%9}, {%0,%1,%2,%3};"
        : "+f"(d[0]), "+f"(d[1]), "+f"(d[2]), "+f"(d[3])
        : "r"(a[0]), "r"(a[1]), "r"(a[2]), "r"(a[3]), "r"(b[0]), "r"(b[1]));
}

__global__ __launch_bounds__(256, 2)
void gemm_mma_kernel(const float* __restrict__ h,
                     const float* __restrict__ W,
                     const float* __restrict__ bias,
                     float* __restrict__ out) {
    __shared__ float As[BM * LDT];
    __shared__ float Ws[BM * LDT];
    __shared__ float sb[OUT_FEAT];

    const int tid  = threadIdx.x;
    const int wid  = tid >> 5;
    const int lane = tid & 31;
    const int group = lane >> 2;
    const int tg    = lane & 3;
    const int block_row = blockIdx.x * BM;

    const int warp_m = (wid & 3) * 32;
    const int warp_n = (wid >> 2) * 64;

    if (tid < OUT_FEAT) sb[tid] = bias[tid];

    const int l_row = tid >> 1;
    const int l_kh  = (tid & 1) * 16;
    const int grow  = block_row + l_row;
    const bool rvalid = (grow < N_NODES);

    float acc[2][8][4];
    #pragma unroll
    for (int mt = 0; mt < 2; mt++)
        #pragma unroll
        for (int nt = 0; nt < 8; nt++)
            #pragma unroll
            for (int r = 0; r < 4; r++) acc[mt][nt][r] = 0.0f;

    for (int c = 0; c < K_TOT / BK; c++) {
        const int k0 = c * BK;
        __syncthreads();

        {
            const int k = k0 + l_kh;
            const float* asrc = (k < IN_FEAT)
                ? (h    + (size_t)grow * IN_FEAT + k)
                : (g_hn + (size_t)grow * IN_FEAT + (k - IN_FEAT));
            float* dsta = &As[l_row * LDT + l_kh];
            #pragma unroll
            for (int i = 0; i < 4; i++) {
                float4 v = rvalid ? reinterpret_cast<const float4*>(asrc)[i]
                                  : make_float4(0.f, 0.f, 0.f, 0.f);
                dsta[i * 4 + 0] = to_tf32(v.x);
                dsta[i * 4 + 1] = to_tf32(v.y);
                dsta[i * 4 + 2] = to_tf32(v.z);
                dsta[i * 4 + 3] = to_tf32(v.w);
            }
        }
        {
            const float* bsrc = W + (size_t)l_row * K_TOT + k0 + l_kh;
            float* dstb = &Ws[l_row * LDT + l_kh];
            #pragma unroll
            for (int i = 0; i < 4; i++) {
                float4 v = reinterpret_cast<const float4*>(bsrc)[i];
                dstb[i * 4 + 0] = to_tf32(v.x);
                dstb[i * 4 + 1] = to_tf32(v.y);
                dstb[i * 4 + 2] = to_tf32(v.z);
                dstb[i * 4 + 3] = to_tf32(v.w);
            }
        }
        __syncthreads();

        #pragma unroll
        for (int ks = 0; ks < 4; ks++) {
            const int k8 = ks * 8;
            uint32_t afr[2][4], bfr[8][2];
            #pragma unroll
            for (int mt = 0; mt < 2; mt++) {
                const float* ap = &As[(warp_m + mt * 16 + group) * LDT + k8];
                afr[mt][0] = __float_as_uint(ap[tg]);
                afr[mt][1] = __float_as_uint(ap[8 * LDT + tg]);
                afr[mt][2] = __float_as_uint(ap[tg + 4]);
                afr[mt][3] = __float_as_uint(ap[8 * LDT + tg + 4]);
            }
            #pragma unroll
            for (int nt = 0; nt < 8; nt++) {
                const float* bp = &Ws[(warp_n + nt * 8 + group) * LDT + k8];
                bfr[nt][0] = __float_as_uint(bp[tg]);
                bfr[nt][1] = __float_as_uint(bp[tg + 4]);
            }
            #pragma unroll
            for (int mt = 0; mt < 2; mt++)
                #pragma unroll
                for (int nt = 0; nt < 8; nt++)
                    mma_tf32(acc[mt][nt], afr[mt], bfr[nt]);
        }
    }

    #pragma unroll
    for (int mt = 0; mt < 2; mt++) {
        const int r0 = block_row + warp_m + mt * 16 + group;
        const int r1 = r0 + 8;
        #pragma unroll
        for (int nt = 0; nt < 8; nt++) {
            const int col = warp_n + nt * 8 + tg * 2;
            const float b0 = sb[col], b1 = sb[col + 1];
            if (r0 < N_NODES) {
                float2 o = make_float2(acc[mt][nt][0] + b0, acc[mt][nt][1] + b1);
                *reinterpret_cast<float2*>(out + (size_t)r0 * OUT_FEAT + col) = o;
            }
            if (r1 < N_NODES) {
                float2 o = make_float2(acc[mt][nt][2] + b0, acc[mt][nt][3] + b1);
                *reinterpret_cast<float2*>(out + (size_t)r1 * OUT_FEAT + col) = o;
            }
        }
    }
}

// ---------------------------------------------------------------------------
extern "C" void kernel_launch(void* const* d_in, const int* in_sizes, int n_in,
                              void* d_out, int out_size) {
    const float* h   = (const float*)d_in[0];
    const void*  src = d_in[1];
    const void*  dst = d_in[2];
    const float* W   = (const float*)d_in[3];
    const float* b   = (const float*)d_in[4];
    float*       out = (float*)d_out;

    const int n_edges = in_sizes[1];

    detect_kernel<<<1, 32>>>(src, n_edges);
    zero_kernel<<<(N_NODES + 255) / 256, 256>>>();
    count_kernel<<<(n_edges + 255) / 256, 256>>>(dst, n_edges);
    scan_phase1<<<NB_SCAN, SCAN_BLK>>>();
    scan_phase2<<<1, 32>>>();
    scan_phase3<<<NB_SCAN, SCAN_BLK>>>();
    fill_kernel<<<(n_edges + 255) / 256, 256>>>(src, dst, n_edges);
    aggregate_kernel<<<(N_NODES * 32 + 255) / 256, 256>>>(h);
    gemm_mma_kernel<<<(N_NODES + BM - 1) / BM, 256>>>(h, W, b, out);
}

// round 6
// speedup vs baseline: 2.8319x; 1.0155x over previous
#include <cuda_runtime.h>
#include <cuda_bf16.h>
#include <cstdint>

#define N_NODES 50000
#define N_EDGES_MAX 800000
#define IN_FEAT 128
#define OUT_FEAT 128
#define K_TOT 256

#define SCAN_BLK 512
#define NB_SCAN ((N_NODES + SCAN_BLK - 1) / SCAN_BLK)   // 98

// ---------------- device scratch (no allocation allowed) ----------------
__device__ float          g_hn[N_NODES * IN_FEAT];   // mean-aggregated (fp32)
__device__ __nv_bfloat16  g_hbf[N_NODES * IN_FEAT];  // bf16 copy of h (12.8MB)
__device__ int   g_count[N_NODES];
__device__ int   g_cursor[N_NODES];
__device__ int   g_off[N_NODES + 1];
__device__ int   g_esrc[N_EDGES_MAX];
__device__ int   g_bsum[NB_SCAN];
__device__ int   g_bbase[NB_SCAN];
__device__ int   g_is64;

// ---------------------------------------------------------------------------
// 0) index dtype detection — parallel across one warp
// ---------------------------------------------------------------------------
__global__ void detect_kernel(const void* __restrict__ src, int n) {
    const long long* p = (const long long*)src;
    int lim = n < 64 ? n : 64;
    int t = threadIdx.x;
    bool bad = false;
    for (int i = t; i < lim; i += 32) {
        long long v = p[i];
        if (v < 0 || v >= (long long)N_NODES) bad = true;
    }
    unsigned m = __ballot_sync(~0u, bad);
    if (t == 0) g_is64 = (m == 0) ? 1 : 0;
}

__device__ __forceinline__ int load_idx(const void* raw, int i) {
    int v = g_is64 ? (int)((const long long*)raw)[i] : ((const int*)raw)[i];
    return min(max(v, 0), N_NODES - 1);
}

// ---------------------------------------------------------------------------
// 1) zero counters + convert h -> bf16 (fused grid-stride)
// ---------------------------------------------------------------------------
__global__ void prep_kernel(const float* __restrict__ h) {
    const int total4 = N_NODES * IN_FEAT / 4;   // 1.6M float4 groups
    for (int i = blockIdx.x * blockDim.x + threadIdx.x; i < total4;
         i += gridDim.x * blockDim.x) {
        float4 v = reinterpret_cast<const float4*>(h)[i];
        __nv_bfloat162 a = __floats2bfloat162_rn(v.x, v.y);
        __nv_bfloat162 b = __floats2bfloat162_rn(v.z, v.w);
        uint2 u;
        u.x = *reinterpret_cast<uint32_t*>(&a);
        u.y = *reinterpret_cast<uint32_t*>(&b);
        reinterpret_cast<uint2*>(g_hbf)[i] = u;
        if (i < N_NODES) { g_count[i] = 0; g_cursor[i] = 0; }
    }
}

// ---------------------------------------------------------------------------
// 2) degree histogram
// ---------------------------------------------------------------------------
__global__ void count_kernel(const void* __restrict__ dst, int n_edges) {
    int i = blockIdx.x * blockDim.x + threadIdx.x;
    if (i < n_edges) atomicAdd(&g_count[load_idx(dst, i)], 1);
}

// ---------------------------------------------------------------------------
// 3) exclusive scan, 3-phase multi-block
// ---------------------------------------------------------------------------
__global__ void scan_phase1() {
    int i = blockIdx.x * SCAN_BLK + threadIdx.x;
    int v = (i < N_NODES) ? g_count[i] : 0;
    __shared__ int ws[SCAN_BLK / 32];
    int lane = threadIdx.x & 31, w = threadIdx.x >> 5;
    #pragma unroll
    for (int o = 16; o > 0; o >>= 1) v += __shfl_down_sync(~0u, v, o);
    if (lane == 0) ws[w] = v;
    __syncthreads();
    if (w == 0) {
        int s = (lane < SCAN_BLK / 32) ? ws[lane] : 0;
        #pragma unroll
        for (int o = 16; o > 0; o >>= 1) s += __shfl_down_sync(~0u, s, o);
        if (lane == 0) g_bsum[blockIdx.x] = s;
    }
}

__global__ void scan_phase2() {          // 1 block, 32 threads
    int lane = threadIdx.x;
    int run = 0;
    for (int base = 0; base < NB_SCAN; base += 32) {
        int idx = base + lane;
        int v = (idx < NB_SCAN) ? g_bsum[idx] : 0;
        int inc = v;
        #pragma unroll
        for (int o = 1; o < 32; o <<= 1) {
            int t = __shfl_up_sync(~0u, inc, o);
            if (lane >= o) inc += t;
        }
        if (idx < NB_SCAN) g_bbase[idx] = inc - v + run;
        run += __shfl_sync(~0u, inc, 31);
    }
    if (lane == 0) g_off[N_NODES] = run;
}

__global__ void scan_phase3() {
    int i = blockIdx.x * SCAN_BLK + threadIdx.x;
    int v = (i < N_NODES) ? g_count[i] : 0;
    __shared__ int ws[SCAN_BLK / 32];
    int lane = threadIdx.x & 31, w = threadIdx.x >> 5;
    int inc = v;
    #pragma unroll
    for (int o = 1; o < 32; o <<= 1) {
        int t = __shfl_up_sync(~0u, inc, o);
        if (lane >= o) inc += t;
    }
    if (lane == 31) ws[w] = inc;
    __syncthreads();
    if (w == 0) {
        int s = (lane < SCAN_BLK / 32) ? ws[lane] : 0;
        int sin = s;
        #pragma unroll
        for (int o = 1; o < 32; o <<= 1) {
            int t = __shfl_up_sync(~0u, sin, o);
            if (lane >= o) sin += t;
        }
        if (lane < SCAN_BLK / 32) ws[lane] = sin - s;
    }
    __syncthreads();
    if (i < N_NODES) g_off[i] = inc - v + ws[w] + g_bbase[blockIdx.x];
}

// ---------------------------------------------------------------------------
// 4) fill per-dst CSR edge lists
// ---------------------------------------------------------------------------
__global__ void fill_kernel(const void* __restrict__ src, const void* __restrict__ dst,
                            int n_edges) {
    int i = blockIdx.x * blockDim.x + threadIdx.x;
    if (i < n_edges) {
        int d = load_idx(dst, i);
        int s = load_idx(src, i);
        int pos = g_off[d] + atomicAdd(&g_cursor[d], 1);
        g_esrc[pos] = s;
    }
}

// ---------------------------------------------------------------------------
// 5) aggregate: one warp per node, bf16 gather (256B/row), fp32 accumulate
// ---------------------------------------------------------------------------
__global__ void aggregate_kernel() {
    int node = (blockIdx.x * blockDim.x + threadIdx.x) >> 5;
    int lane = threadIdx.x & 31;
    if (node >= N_NODES) return;

    int beg = g_off[node];
    int end = g_off[node + 1];
    int cnt = end - beg;

    float4 acc0 = make_float4(0.f, 0.f, 0.f, 0.f);
    float4 acc1 = make_float4(0.f, 0.f, 0.f, 0.f);
    int i = beg;
    for (; i + 1 < end; i += 2) {
        int s0 = g_esrc[i];
        int s1 = g_esrc[i + 1];
        uint2 u0 = reinterpret_cast<const uint2*>(g_hbf + (size_t)s0 * IN_FEAT)[lane];
        uint2 u1 = reinterpret_cast<const uint2*>(g_hbf + (size_t)s1 * IN_FEAT)[lane];
        float2 a0 = __bfloat1622float2(*reinterpret_cast<__nv_bfloat162*>(&u0.x));
        float2 b0 = __bfloat1622float2(*reinterpret_cast<__nv_bfloat162*>(&u0.y));
        float2 a1 = __bfloat1622float2(*reinterpret_cast<__nv_bfloat162*>(&u1.x));
        float2 b1 = __bfloat1622float2(*reinterpret_cast<__nv_bfloat162*>(&u1.y));
        acc0.x += a0.x; acc0.y += a0.y; acc0.z += b0.x; acc0.w += b0.y;
        acc1.x += a1.x; acc1.y += a1.y; acc1.z += b1.x; acc1.w += b1.y;
    }
    if (i < end) {
        int s = g_esrc[i];
        uint2 u = reinterpret_cast<const uint2*>(g_hbf + (size_t)s * IN_FEAT)[lane];
        float2 a = __bfloat1622float2(*reinterpret_cast<__nv_bfloat162*>(&u.x));
        float2 b = __bfloat1622float2(*reinterpret_cast<__nv_bfloat162*>(&u.y));
        acc0.x += a.x; acc0.y += a.y; acc0.z += b.x; acc0.w += b.y;
    }
    float inv = 1.0f / fmaxf((float)cnt, 1.0f);
    acc0.x = (acc0.x + acc1.x) * inv;
    acc0.y = (acc0.y + acc1.y) * inv;
    acc0.z = (acc0.z + acc1.z) * inv;
    acc0.w = (acc0.w + acc1.w) * inv;
    reinterpret_cast<float4*>(g_hn + (size_t)node * IN_FEAT)[lane] = acc0;
}

// ---------------------------------------------------------------------------
// 6) tf32 mma.sync GEMM: out[128 x 128] per CTA = [h | g_hn] @ W^T + b
// ---------------------------------------------------------------------------
#define BM 128
#define BK 32
#define LDT 36

__device__ __forceinline__ float to_tf32(float x) {
    float y;
    asm("cvt.rna.tf32.f32 %0, %1;" : "=f"(y) : "f"(x));
    return y;
}

__device__ __forceinline__ void mma_tf32(float* d, const uint32_t* a, const uint32_t* b) {
    asm volatile(
        "mma.sync.aligned.m16n8k8.row.col.f32.tf32.tf32.f32 "
        "{%0,%1,%2,%3}, {%4,%5,%6,%7}, {%8,%9}, {%0,%1,%2,%3};"
        : "+f"(d[0]), "+f"(d[1]), "+f"(d[2]), "+f"(d[3])
        : "r"(a[0]), "r"(a[1]), "r"(a[2]), "r"(a[3]), "r"(b[0]), "r"(b[1]));
}

__global__ __launch_bounds__(256, 2)
void gemm_mma_kernel(const float* __restrict__ h,
                     const float* __restrict__ W,
                     const float* __restrict__ bias,
                     float* __restrict__ out) {
    __shared__ float As[BM * LDT];
    __shared__ float Ws[BM * LDT];
    __shared__ float sb[OUT_FEAT];

    const int tid  = threadIdx.x;
    const int wid  = tid >> 5;
    const int lane = tid & 31;
    const int group = lane >> 2;
    const int tg    = lane & 3;
    const int block_row = blockIdx.x * BM;

    const int warp_m = (wid & 3) * 32;
    const int warp_n = (wid >> 2) * 64;

    if (tid < OUT_FEAT) sb[tid] = bias[tid];

    const int l_row = tid >> 1;
    const int l_kh  = (tid & 1) * 16;
    const int grow  = block_row + l_row;
    const bool rvalid = (grow < N_NODES);

    float acc[2][8][4];
    #pragma unroll
    for (int mt = 0; mt < 2; mt++)
        #pragma unroll
        for (int nt = 0; nt < 8; nt++)
            #pragma unroll
            for (int r = 0; r < 4; r++) acc[mt][nt][r] = 0.0f;

    for (int c = 0; c < K_TOT / BK; c++) {
        const int k0 = c * BK;
        __syncthreads();

        {
            const int k = k0 + l_kh;
            const float* asrc = (k < IN_FEAT)
                ? (h    + (size_t)grow * IN_FEAT + k)
                : (g_hn + (size_t)grow * IN_FEAT + (k - IN_FEAT));
            float* dsta = &As[l_row * LDT + l_kh];
            #pragma unroll
            for (int i = 0; i < 4; i++) {
                float4 v = rvalid ? reinterpret_cast<const float4*>(asrc)[i]
                                  : make_float4(0.f, 0.f, 0.f, 0.f);
                dsta[i * 4 + 0] = to_tf32(v.x);
                dsta[i * 4 + 1] = to_tf32(v.y);
                dsta[i * 4 + 2] = to_tf32(v.z);
                dsta[i * 4 + 3] = to_tf32(v.w);
            }
        }
        {
            const float* bsrc = W + (size_t)l_row * K_TOT + k0 + l_kh;
            float* dstb = &Ws[l_row * LDT + l_kh];
            #pragma unroll
            for (int i = 0; i < 4; i++) {
                float4 v = reinterpret_cast<const float4*>(bsrc)[i];
                dstb[i * 4 + 0] = to_tf32(v.x);
                dstb[i * 4 + 1] = to_tf32(v.y);
                dstb[i * 4 + 2] = to_tf32(v.z);
                dstb[i * 4 + 3] = to_tf32(v.w);
            }
        }
        __syncthreads();

        #pragma unroll
        for (int ks = 0; ks < 4; ks++) {
            const int k8 = ks * 8;
            uint32_t afr[2][4], bfr[8][2];
            #pragma unroll
            for (int mt = 0; mt < 2; mt++) {
                const float* ap = &As[(warp_m + mt * 16 + group) * LDT + k8];
                afr[mt][0] = __float_as_uint(ap[tg]);
                afr[mt][1] = __float_as_uint(ap[8 * LDT + tg]);
                afr[mt][2] = __float_as_uint(ap[tg + 4]);
                afr[mt][3] = __float_as_uint(ap[8 * LDT + tg + 4]);
            }
            #pragma unroll
            for (int nt = 0; nt < 8; nt++) {
                const float* bp = &Ws[(warp_n + nt * 8 + group) * LDT + k8];
                bfr[nt][0] = __float_as_uint(bp[tg]);
                bfr[nt][1] = __float_as_uint(bp[tg + 4]);
            }
            #pragma unroll
            for (int mt = 0; mt < 2; mt++)
                #pragma unroll
                for (int nt = 0; nt < 8; nt++)
                    mma_tf32(acc[mt][nt], afr[mt], bfr[nt]);
        }
    }

    #pragma unroll
    for (int mt = 0; mt < 2; mt++) {
        const int r0 = block_row + warp_m + mt * 16 + group;
        const int r1 = r0 + 8;
        #pragma unroll
        for (int nt = 0; nt < 8; nt++) {
            const int col = warp_n + nt * 8 + tg * 2;
            const float b0 = sb[col], b1 = sb[col + 1];
            if (r0 < N_NODES) {
                float2 o = make_float2(acc[mt][nt][0] + b0, acc[mt][nt][1] + b1);
                *reinterpret_cast<float2*>(out + (size_t)r0 * OUT_FEAT + col) = o;
            }
            if (r1 < N_NODES) {
                float2 o = make_float2(acc[mt][nt][2] + b0, acc[mt][nt][3] + b1);
                *reinterpret_cast<float2*>(out + (size_t)r1 * OUT_FEAT + col) = o;
            }
        }
    }
}

// ---------------------------------------------------------------------------
extern "C" void kernel_launch(void* const* d_in, const int* in_sizes, int n_in,
                              void* d_out, int out_size) {
    const float* h   = (const float*)d_in[0];
    const void*  src = d_in[1];
    const void*  dst = d_in[2];
    const float* W   = (const float*)d_in[3];
    const float* b   = (const float*)d_in[4];
    float*       out = (float*)d_out;

    const int n_edges = in_sizes[1];

    detect_kernel<<<1, 32>>>(src, n_edges);
    prep_kernel<<<2048, 256>>>(h);
    count_kernel<<<(n_edges + 255) / 256, 256>>>(dst, n_edges);
    scan_phase1<<<NB_SCAN, SCAN_BLK>>>();
    scan_phase2<<<1, 32>>>();
    scan_phase3<<<NB_SCAN, SCAN_BLK>>>();
    fill_kernel<<<(n_edges + 255) / 256, 256>>>(src, dst, n_edges);
    aggregate_kernel<<<(N_NODES * 32 + 255) / 256, 256>>>();
    gemm_mma_kernel<<<(N_NODES + BM - 1) / BM, 256>>>(h, W, b, out);
}

// round 7
// speedup vs baseline: 2.8905x; 1.0207x over previous
#include <cuda_runtime.h>
#include <cuda_bf16.h>
#include <cstdint>

#define N_NODES 50000
#define N_EDGES_MAX 800000
#define IN_FEAT 128
#define OUT_FEAT 128
#define K_TOT 256

#define SCAN_BLK 512
#define NB_SCAN ((N_NODES + SCAN_BLK - 1) / SCAN_BLK)   // 98

// ---------------- device scratch (no allocation allowed) ----------------
__device__ float          g_hn[N_NODES * IN_FEAT];   // mean-aggregated (fp32)
__device__ __nv_bfloat16  g_hbf[N_NODES * IN_FEAT];  // bf16 copy of h (12.8MB)
__device__ int   g_count[N_NODES];
__device__ int   g_cursor[N_NODES];
__device__ int   g_off[N_NODES + 1];
__device__ int   g_esrc[N_EDGES_MAX];
__device__ int   g_bsum[NB_SCAN];
__device__ int   g_bbase[NB_SCAN];
__device__ int   g_is64;

// ---------------------------------------------------------------------------
// 0) index dtype detection — parallel across one warp
// ---------------------------------------------------------------------------
__global__ void detect_kernel(const void* __restrict__ src, int n) {
    const long long* p = (const long long*)src;
    int lim = n < 64 ? n : 64;
    int t = threadIdx.x;
    bool bad = false;
    for (int i = t; i < lim; i += 32) {
        long long v = p[i];
        if (v < 0 || v >= (long long)N_NODES) bad = true;
    }
    unsigned m = __ballot_sync(~0u, bad);
    if (t == 0) g_is64 = (m == 0) ? 1 : 0;
}

__device__ __forceinline__ int load_idx(const void* raw, int i) {
    int v = g_is64 ? (int)((const long long*)raw)[i] : ((const int*)raw)[i];
    return min(max(v, 0), N_NODES - 1);
}

// ---------------------------------------------------------------------------
// 1a) zero counters (main stream, ahead of count)
// ---------------------------------------------------------------------------
__global__ void zero_kernel() {
    int i = blockIdx.x * blockDim.x + threadIdx.x;
    if (i < N_NODES) { g_count[i] = 0; g_cursor[i] = 0; }
}

// ---------------------------------------------------------------------------
// 1b) convert h -> bf16 (side stream, overlaps count/scan/fill)
// ---------------------------------------------------------------------------
__global__ void convert_kernel(const float* __restrict__ h) {
    const int total4 = N_NODES * IN_FEAT / 4;
    for (int i = blockIdx.x * blockDim.x + threadIdx.x; i < total4;
         i += gridDim.x * blockDim.x) {
        float4 v = reinterpret_cast<const float4*>(h)[i];
        __nv_bfloat162 a = __floats2bfloat162_rn(v.x, v.y);
        __nv_bfloat162 b = __floats2bfloat162_rn(v.z, v.w);
        uint2 u;
        u.x = *reinterpret_cast<uint32_t*>(&a);
        u.y = *reinterpret_cast<uint32_t*>(&b);
        reinterpret_cast<uint2*>(g_hbf)[i] = u;
    }
}

// ---------------------------------------------------------------------------
// 2) degree histogram
// ---------------------------------------------------------------------------
__global__ void count_kernel(const void* __restrict__ dst, int n_edges) {
    int i = blockIdx.x * blockDim.x + threadIdx.x;
    if (i < n_edges) atomicAdd(&g_count[load_idx(dst, i)], 1);
}

// ---------------------------------------------------------------------------
// 3) exclusive scan, 3-phase multi-block
// ---------------------------------------------------------------------------
__global__ void scan_phase1() {
    int i = blockIdx.x * SCAN_BLK + threadIdx.x;
    int v = (i < N_NODES) ? g_count[i] : 0;
    __shared__ int ws[SCAN_BLK / 32];
    int lane = threadIdx.x & 31, w = threadIdx.x >> 5;
    #pragma unroll
    for (int o = 16; o > 0; o >>= 1) v += __shfl_down_sync(~0u, v, o);
    if (lane == 0) ws[w] = v;
    __syncthreads();
    if (w == 0) {
        int s = (lane < SCAN_BLK / 32) ? ws[lane] : 0;
        #pragma unroll
        for (int o = 16; o > 0; o >>= 1) s += __shfl_down_sync(~0u, s, o);
        if (lane == 0) g_bsum[blockIdx.x] = s;
    }
}

__global__ void scan_phase2() {
    int lane = threadIdx.x;
    int run = 0;
    for (int base = 0; base < NB_SCAN; base += 32) {
        int idx = base + lane;
        int v = (idx < NB_SCAN) ? g_bsum[idx] : 0;
        int inc = v;
        #pragma unroll
        for (int o = 1; o < 32; o <<= 1) {
            int t = __shfl_up_sync(~0u, inc, o);
            if (lane >= o) inc += t;
        }
        if (idx < NB_SCAN) g_bbase[idx] = inc - v + run;
        run += __shfl_sync(~0u, inc, 31);
    }
    if (lane == 0) g_off[N_NODES] = run;
}

__global__ void scan_phase3() {
    int i = blockIdx.x * SCAN_BLK + threadIdx.x;
    int v = (i < N_NODES) ? g_count[i] : 0;
    __shared__ int ws[SCAN_BLK / 32];
    int lane = threadIdx.x & 31, w = threadIdx.x >> 5;
    int inc = v;
    #pragma unroll
    for (int o = 1; o < 32; o <<= 1) {
        int t = __shfl_up_sync(~0u, inc, o);
        if (lane >= o) inc += t;
    }
    if (lane == 31) ws[w] = inc;
    __syncthreads();
    if (w == 0) {
        int s = (lane < SCAN_BLK / 32) ? ws[lane] : 0;
        int sin = s;
        #pragma unroll
        for (int o = 1; o < 32; o <<= 1) {
            int t = __shfl_up_sync(~0u, sin, o);
            if (lane >= o) sin += t;
        }
        if (lane < SCAN_BLK / 32) ws[lane] = sin - s;
    }
    __syncthreads();
    if (i < N_NODES) g_off[i] = inc - v + ws[w] + g_bbase[blockIdx.x];
}

// ---------------------------------------------------------------------------
// 4) fill per-dst CSR edge lists
// ---------------------------------------------------------------------------
__global__ void fill_kernel(const void* __restrict__ src, const void* __restrict__ dst,
                            int n_edges) {
    int i = blockIdx.x * blockDim.x + threadIdx.x;
    if (i < n_edges) {
        int d = load_idx(dst, i);
        int s = load_idx(src, i);
        int pos = g_off[d] + atomicAdd(&g_cursor[d], 1);
        g_esrc[pos] = s;
    }
}

// ---------------------------------------------------------------------------
// 5) aggregate: one warp per node, bf16 gather, fp32 accumulate
// ---------------------------------------------------------------------------
__global__ void aggregate_kernel() {
    int node = (blockIdx.x * blockDim.x + threadIdx.x) >> 5;
    int lane = threadIdx.x & 31;
    if (node >= N_NODES) return;

    int beg = g_off[node];
    int end = g_off[node + 1];
    int cnt = end - beg;

    float4 acc0 = make_float4(0.f, 0.f, 0.f, 0.f);
    float4 acc1 = make_float4(0.f, 0.f, 0.f, 0.f);
    int i = beg;
    for (; i + 1 < end; i += 2) {
        int s0 = g_esrc[i];
        int s1 = g_esrc[i + 1];
        uint2 u0 = reinterpret_cast<const uint2*>(g_hbf + (size_t)s0 * IN_FEAT)[lane];
        uint2 u1 = reinterpret_cast<const uint2*>(g_hbf + (size_t)s1 * IN_FEAT)[lane];
        float2 a0 = __bfloat1622float2(*reinterpret_cast<__nv_bfloat162*>(&u0.x));
        float2 b0 = __bfloat1622float2(*reinterpret_cast<__nv_bfloat162*>(&u0.y));
        float2 a1 = __bfloat1622float2(*reinterpret_cast<__nv_bfloat162*>(&u1.x));
        float2 b1 = __bfloat1622float2(*reinterpret_cast<__nv_bfloat162*>(&u1.y));
        acc0.x += a0.x; acc0.y += a0.y; acc0.z += b0.x; acc0.w += b0.y;
        acc1.x += a1.x; acc1.y += a1.y; acc1.z += b1.x; acc1.w += b1.y;
    }
    if (i < end) {
        int s = g_esrc[i];
        uint2 u = reinterpret_cast<const uint2*>(g_hbf + (size_t)s * IN_FEAT)[lane];
        float2 a = __bfloat1622float2(*reinterpret_cast<__nv_bfloat162*>(&u.x));
        float2 b = __bfloat1622float2(*reinterpret_cast<__nv_bfloat162*>(&u.y));
        acc0.x += a.x; acc0.y += a.y; acc0.z += b.x; acc0.w += b.y;
    }
    float inv = 1.0f / fmaxf((float)cnt, 1.0f);
    acc0.x = (acc0.x + acc1.x) * inv;
    acc0.y = (acc0.y + acc1.y) * inv;
    acc0.z = (acc0.z + acc1.z) * inv;
    acc0.w = (acc0.w + acc1.w) * inv;
    reinterpret_cast<float4*>(g_hn + (size_t)node * IN_FEAT)[lane] = acc0;
}

// ---------------------------------------------------------------------------
// 6) tf32 mma GEMM with register prefetch + vector STS
// ---------------------------------------------------------------------------
#define BM 128
#define BK 32
#define LDT 36

__device__ __forceinline__ float to_tf32(float x) {
    float y;
    asm("cvt.rna.tf32.f32 %0, %1;" : "=f"(y) : "f"(x));
    return y;
}

__device__ __forceinline__ void mma_tf32(float* d, const uint32_t* a, const uint32_t* b) {
    asm volatile(
        "mma.sync.aligned.m16n8k8.row.col.f32.tf32.tf32.f32 "
        "{%0,%1,%2,%3}, {%4,%5,%6,%7}, {%8,%9}, {%0,%1,%2,%3};"
        : "+f"(d[0]), "+f"(d[1]), "+f"(d[2]), "+f"(d[3])
        : "r"(a[0]), "r"(a[1]), "r"(a[2]), "r"(a[3]), "r"(b[0]), "r"(b[1]));
}

__global__ __launch_bounds__(256, 2)
void gemm_mma_kernel(const float* __restrict__ h,
                     const float* __restrict__ W,
                     const float* __restrict__ bias,
                     float* __restrict__ out) {
    __shared__ float As[BM * LDT];
    __shared__ float Ws[BM * LDT];
    __shared__ float sb[OUT_FEAT];

    const int tid  = threadIdx.x;
    const int wid  = tid >> 5;
    const int lane = tid & 31;
    const int group = lane >> 2;
    const int tg    = lane & 3;
    const int block_row = blockIdx.x * BM;

    const int warp_m = (wid & 3) * 32;
    const int warp_n = (wid >> 2) * 64;

    if (tid < OUT_FEAT) sb[tid] = bias[tid];

    const int l_row = tid >> 1;
    const int l_kh  = (tid & 1) * 16;
    const int grow  = block_row + l_row;
    const bool rvalid = (grow < N_NODES);

    float acc[2][8][4];
    #pragma unroll
    for (int mt = 0; mt < 2; mt++)
        #pragma unroll
        for (int nt = 0; nt < 8; nt++)
            #pragma unroll
            for (int r = 0; r < 4; r++) acc[mt][nt][r] = 0.0f;

    // register staging for prefetch
    float4 av[4], bv[4];

    // load chunk 0
    {
        const int k = l_kh;           // k0 = 0 -> always from h
        const float* asrc = h + (size_t)grow * IN_FEAT + k;
        const float* bsrc = W + (size_t)l_row * K_TOT + k;
        #pragma unroll
        for (int i = 0; i < 4; i++) {
            av[i] = rvalid ? reinterpret_cast<const float4*>(asrc)[i]
                           : make_float4(0.f, 0.f, 0.f, 0.f);
            bv[i] = reinterpret_cast<const float4*>(bsrc)[i];
        }
    }

    for (int c = 0; c < K_TOT / BK; c++) {
        // ---- store staged regs to smem (cvt + STS.128) ----
        float* dsta = &As[l_row * LDT + l_kh];
        float* dstb = &Ws[l_row * LDT + l_kh];
        #pragma unroll
        for (int i = 0; i < 4; i++) {
            float4 a4 = make_float4(to_tf32(av[i].x), to_tf32(av[i].y),
                                    to_tf32(av[i].z), to_tf32(av[i].w));
            float4 b4 = make_float4(to_tf32(bv[i].x), to_tf32(bv[i].y),
                                    to_tf32(bv[i].z), to_tf32(bv[i].w));
            *reinterpret_cast<float4*>(dsta + i * 4) = a4;
            *reinterpret_cast<float4*>(dstb + i * 4) = b4;
        }
        __syncthreads();

        // ---- prefetch next chunk into regs (latency hidden by MMAs) ----
        if (c + 1 < K_TOT / BK) {
            const int k = (c + 1) * BK + l_kh;
            const float* asrc = (k < IN_FEAT)
                ? (h    + (size_t)grow * IN_FEAT + k)
                : (g_hn + (size_t)grow * IN_FEAT + (k - IN_FEAT));
            const float* bsrc = W + (size_t)l_row * K_TOT + k;
            #pragma unroll
            for (int i = 0; i < 4; i++) {
                av[i] = rvalid ? reinterpret_cast<const float4*>(asrc)[i]
                               : make_float4(0.f, 0.f, 0.f, 0.f);
                bv[i] = reinterpret_cast<const float4*>(bsrc)[i];
            }
        }

        // ---- MMAs for chunk c ----
        #pragma unroll
        for (int ks = 0; ks < 4; ks++) {
            const int k8 = ks * 8;
            uint32_t afr[2][4], bfr[8][2];
            #pragma unroll
            for (int mt = 0; mt < 2; mt++) {
                const float* ap = &As[(warp_m + mt * 16 + group) * LDT + k8];
                afr[mt][0] = __float_as_uint(ap[tg]);
                afr[mt][1] = __float_as_uint(ap[8 * LDT + tg]);
                afr[mt][2] = __float_as_uint(ap[tg + 4]);
                afr[mt][3] = __float_as_uint(ap[8 * LDT + tg + 4]);
            }
            #pragma unroll
            for (int nt = 0; nt < 8; nt++) {
                const float* bp = &Ws[(warp_n + nt * 8 + group) * LDT + k8];
                bfr[nt][0] = __float_as_uint(bp[tg]);
                bfr[nt][1] = __float_as_uint(bp[tg + 4]);
            }
            #pragma unroll
            for (int mt = 0; mt < 2; mt++)
                #pragma unroll
                for (int nt = 0; nt < 8; nt++)
                    mma_tf32(acc[mt][nt], afr[mt], bfr[nt]);
        }
        __syncthreads();
    }

    #pragma unroll
    for (int mt = 0; mt < 2; mt++) {
        const int r0 = block_row + warp_m + mt * 16 + group;
        const int r1 = r0 + 8;
        #pragma unroll
        for (int nt = 0; nt < 8; nt++) {
            const int col = warp_n + nt * 8 + tg * 2;
            const float b0 = sb[col], b1 = sb[col + 1];
            if (r0 < N_NODES) {
                float2 o = make_float2(acc[mt][nt][0] + b0, acc[mt][nt][1] + b1);
                *reinterpret_cast<float2*>(out + (size_t)r0 * OUT_FEAT + col) = o;
            }
            if (r1 < N_NODES) {
                float2 o = make_float2(acc[mt][nt][2] + b0, acc[mt][nt][3] + b1);
                *reinterpret_cast<float2*>(out + (size_t)r1 * OUT_FEAT + col) = o;
            }
        }
    }
}

// ---------------------------------------------------------------------------
extern "C" void kernel_launch(void* const* d_in, const int* in_sizes, int n_in,
                              void* d_out, int out_size) {
    const float* h   = (const float*)d_in[0];
    const void*  src = d_in[1];
    const void*  dst = d_in[2];
    const float* W   = (const float*)d_in[3];
    const float* b   = (const float*)d_in[4];
    float*       out = (float*)d_out;

    const int n_edges = in_sizes[1];

    // one-time host resources (not device memory; deterministic work per call)
    static cudaStream_t s_side = nullptr;
    static cudaEvent_t  ev_fork = nullptr, ev_join = nullptr;
    if (s_side == nullptr) {
        cudaStreamCreateWithFlags(&s_side, cudaStreamNonBlocking);
        cudaEventCreateWithFlags(&ev_fork, cudaEventDisableTiming);
        cudaEventCreateWithFlags(&ev_join, cudaEventDisableTiming);
    }

    // main stream: CSR chain
    detect_kernel<<<1, 32>>>(src, n_edges);
    zero_kernel<<<(N_NODES + 255) / 256, 256>>>();

    // fork: bf16 conversion runs concurrently with count/scan/fill
    cudaEventRecord(ev_fork, 0);
    cudaStreamWaitEvent(s_side, ev_fork, 0);
    convert_kernel<<<2048, 256, 0, s_side>>>(h);
    cudaEventRecord(ev_join, s_side);

    count_kernel<<<(n_edges + 255) / 256, 256>>>(dst, n_edges);
    scan_phase1<<<NB_SCAN, SCAN_BLK>>>();
    scan_phase2<<<1, 32>>>();
    scan_phase3<<<NB_SCAN, SCAN_BLK>>>();
    fill_kernel<<<(n_edges + 255) / 256, 256>>>(src, dst, n_edges);

    // join: aggregate needs g_hbf
    cudaStreamWaitEvent(0, ev_join, 0);
    aggregate_kernel<<<(N_NODES * 32 + 255) / 256, 256>>>();
    gemm_mma_kernel<<<(N_NODES + BM - 1) / BM, 256>>>(h, W, b, out);
}